// round 1
// baseline (speedup 1.0000x reference)
#include <cuda_runtime.h>
#include <math.h>

#define Bb 2
#define Nn 2048
#define Cc 1024
#define Hh 16
#define Dd 64
#define Mtot (Bb*Nn)     /* 4096 */
#define K3  (3*Cc)       /* 3072 */
#define SCALE 0.125f     /* 1/sqrt(64) */

// ---------------- scratch (static device arrays; no runtime alloc) ----------
__device__ float g_q[(size_t)Bb*Hh*Nn*Dd];   // [B,H,N,D]
__device__ float g_k[(size_t)Bb*Hh*Nn*Dd];
__device__ float g_v[(size_t)Bb*Hh*Nn*Dd];
__device__ float g_o[(size_t)Mtot*Cc];       // attention out, [B,N,H,D] = [4096,1024]
__device__ float g_cos[Nn*(Dd/2)];
__device__ float g_sin[Nn*(Dd/2)];

// ---------------- RoPE tables ----------------
__global__ void rope_init_kernel() {
    int idx = blockIdx.x * blockDim.x + threadIdx.x;
    if (idx >= Nn * (Dd/2)) return;
    int n = idx / (Dd/2);
    int i = idx % (Dd/2);
    // inv_freq = 10000^(-(2i)/D) = 10000^(-i/32)
    float invf = powf(10000.0f, -(float)i / (float)(Dd/2));
    float f = (float)n * invf;
    g_cos[idx] = cosf(f);
    g_sin[idx] = sinf(f);
}

// ---------------- GEMM1: qkv = x @ Wqkv, fused RoPE epilogue ----------------
// A: [4096,1024] row-major (x). B: [1024,3072] row-major (Wqkv).
// 128x128 block tile, BK=8, 256 threads, 8x8 per thread.
__global__ __launch_bounds__(256) void qkv_rope_gemm(
    const float* __restrict__ A, const float* __restrict__ Bw)
{
    __shared__ float As[8][128];
    __shared__ float Bs[8][128];

    int tid = threadIdx.x;
    int bm = blockIdx.y * 128;
    int bn = blockIdx.x * 128;
    int tx = tid & 15, ty = tid >> 4;

    float acc[8][8];
#pragma unroll
    for (int i = 0; i < 8; i++)
#pragma unroll
        for (int j = 0; j < 8; j++) acc[i][j] = 0.0f;

    int arow = tid >> 1, ac4 = (tid & 1) * 4;
    int brow = tid >> 5, bc4 = (tid & 31) * 4;
    const float* Aptr = A + (size_t)(bm + arow) * Cc + ac4;
    const float* Bptr = Bw + (size_t)brow * K3 + bn + bc4;

    for (int kt = 0; kt < Cc / 8; kt++) {
        float4 av = *(const float4*)Aptr;
        As[ac4 + 0][arow] = av.x;
        As[ac4 + 1][arow] = av.y;
        As[ac4 + 2][arow] = av.z;
        As[ac4 + 3][arow] = av.w;
        *(float4*)&Bs[brow][bc4] = *(const float4*)Bptr;
        __syncthreads();

        float a[8], bb[8];
#pragma unroll
        for (int k = 0; k < 8; k++) {
            *(float4*)&a[0]  = *(const float4*)&As[k][ty * 4];
            *(float4*)&a[4]  = *(const float4*)&As[k][ty * 4 + 64];
            *(float4*)&bb[0] = *(const float4*)&Bs[k][tx * 4];
            *(float4*)&bb[4] = *(const float4*)&Bs[k][tx * 4 + 64];
#pragma unroll
            for (int i = 0; i < 8; i++)
#pragma unroll
                for (int j = 0; j < 8; j++) acc[i][j] = fmaf(a[i], bb[j], acc[i][j]);
        }
        __syncthreads();
        Aptr += 8;
        Bptr += 8 * K3;
    }

    // Epilogue: split into q/k/v, apply RoPE to q,k; store as [B,H,N,D].
#pragma unroll
    for (int s = 0; s < 2; s++) {
#pragma unroll
        for (int i = 0; i < 4; i++) {
            int row = bm + s * 64 + ty * 4 + i;
            int b = row >> 11;       // / 2048
            int n = row & 2047;
#pragma unroll
            for (int t = 0; t < 2; t++) {
                int col = bn + t * 64 + tx * 4;
                int region = col >> 10;   // 0=q,1=k,2=v
                int cc = col & 1023;
                int h = cc >> 6;
                int dd = cc & 63;         // multiple of 4
                float y0 = acc[s * 4 + i][t * 4 + 0];
                float y1 = acc[s * 4 + i][t * 4 + 1];
                float y2 = acc[s * 4 + i][t * 4 + 2];
                float y3 = acc[s * 4 + i][t * 4 + 3];
                size_t base = ((size_t)(b * Hh + h) * Nn + n) * Dd;
                if (region == 2) {
                    float4 v4 = make_float4(y0, y1, y2, y3);
                    *(float4*)(g_v + base + dd) = v4;
                } else {
                    float* dst = (region == 0) ? g_q : g_k;
                    int i1 = dd >> 1;   // even; pairs (dd,dd+1)->i1, (dd+2,dd+3)->i1+1
                    float c0 = g_cos[n * 32 + i1],     s0 = g_sin[n * 32 + i1];
                    float c1 = g_cos[n * 32 + i1 + 1], s1 = g_sin[n * 32 + i1 + 1];
                    dst[base + i1]      = y0 * c0 - y1 * s0;
                    dst[base + i1 + 32] = y0 * s0 + y1 * c0;
                    dst[base + i1 + 1]      = y2 * c1 - y3 * s1;
                    dst[base + i1 + 1 + 32] = y2 * s1 + y3 * c1;
                }
            }
        }
    }
}

// ---------------- Flash attention (causal), fp32 SIMT ----------------
// Block = (b,h, 64-query tile); 256 threads as 16x16; per thread 4 q-rows,
// 4 key-cols (for S) / 4 out-dims (for O).
#define SROW 68   // padded row stride in shared
__global__ __launch_bounds__(256) void flash_attn_kernel()
{
    extern __shared__ float sm[];
    float* Qs = sm;
    float* Ks = sm + 64 * SROW;
    float* Vs = sm + 2 * 64 * SROW;
    float* Ps = sm + 3 * 64 * SROW;

    int tid = threadIdx.x;
    int tx = tid & 15, ty = tid >> 4;
    int bh = blockIdx.y;      // b*H + h
    int qb = blockIdx.x;      // query tile index
    int b = bh / Hh, h = bh % Hh;

    const float* Qp = g_q + (size_t)bh * Nn * Dd + (size_t)qb * 64 * Dd;
    const float* Kp = g_k + (size_t)bh * Nn * Dd;
    const float* Vp = g_v + (size_t)bh * Nn * Dd;

    // load Q tile [64][64]
#pragma unroll
    for (int t = 0; t < 4; t++) {
        int idx = tid + t * 256;
        int r = idx >> 4, c = (idx & 15) << 2;
        *(float4*)&Qs[r * SROW + c] = *(const float4*)(Qp + r * Dd + c);
    }

    float m[4], l[4];
    float4 o[4];
#pragma unroll
    for (int i = 0; i < 4; i++) {
        m[i] = -1e30f; l[i] = 0.0f;
        o[i] = make_float4(0.f, 0.f, 0.f, 0.f);
    }
    __syncthreads();

    for (int kb = 0; kb <= qb; kb++) {
        // load K,V tiles
        const float* Kt = Kp + (size_t)kb * 64 * Dd;
        const float* Vt = Vp + (size_t)kb * 64 * Dd;
#pragma unroll
        for (int t = 0; t < 4; t++) {
            int idx = tid + t * 256;
            int r = idx >> 4, c = (idx & 15) << 2;
            *(float4*)&Ks[r * SROW + c] = *(const float4*)(Kt + r * Dd + c);
            *(float4*)&Vs[r * SROW + c] = *(const float4*)(Vt + r * Dd + c);
        }
        __syncthreads();

        // S = Q K^T * scale
        float s[4][4];
#pragma unroll
        for (int i = 0; i < 4; i++)
#pragma unroll
            for (int j = 0; j < 4; j++) s[i][j] = 0.0f;

#pragma unroll
        for (int d4 = 0; d4 < 16; d4++) {
            float4 qv[4], kv[4];
#pragma unroll
            for (int i = 0; i < 4; i++) qv[i] = *(float4*)&Qs[(ty * 4 + i) * SROW + d4 * 4];
#pragma unroll
            for (int j = 0; j < 4; j++) kv[j] = *(float4*)&Ks[(tx * 4 + j) * SROW + d4 * 4];
#pragma unroll
            for (int i = 0; i < 4; i++)
#pragma unroll
                for (int j = 0; j < 4; j++) {
                    s[i][j] = fmaf(qv[i].x, kv[j].x, s[i][j]);
                    s[i][j] = fmaf(qv[i].y, kv[j].y, s[i][j]);
                    s[i][j] = fmaf(qv[i].z, kv[j].z, s[i][j]);
                    s[i][j] = fmaf(qv[i].w, kv[j].w, s[i][j]);
                }
        }

        bool diag = (kb == qb);
#pragma unroll
        for (int i = 0; i < 4; i++) {
            int qg = qb * 64 + ty * 4 + i;
#pragma unroll
            for (int j = 0; j < 4; j++) {
                s[i][j] *= SCALE;
                if (diag) {
                    int kg = kb * 64 + tx * 4 + j;
                    if (kg > qg) s[i][j] = -1e30f;
                }
            }
        }

        // online softmax
#pragma unroll
        for (int i = 0; i < 4; i++) {
            float rm = fmaxf(fmaxf(s[i][0], s[i][1]), fmaxf(s[i][2], s[i][3]));
#pragma unroll
            for (int off = 8; off >= 1; off >>= 1)
                rm = fmaxf(rm, __shfl_xor_sync(0xffffffffu, rm, off));
            float mnew = fmaxf(m[i], rm);
            float alpha = __expf(m[i] - mnew);
            float p0 = __expf(s[i][0] - mnew);
            float p1 = __expf(s[i][1] - mnew);
            float p2 = __expf(s[i][2] - mnew);
            float p3 = __expf(s[i][3] - mnew);
            float rs = p0 + p1 + p2 + p3;
#pragma unroll
            for (int off = 8; off >= 1; off >>= 1)
                rs += __shfl_xor_sync(0xffffffffu, rs, off);
            l[i] = l[i] * alpha + rs;
            o[i].x *= alpha; o[i].y *= alpha; o[i].z *= alpha; o[i].w *= alpha;
            m[i] = mnew;
            int r = ty * 4 + i;
            Ps[r * SROW + tx * 4 + 0] = p0;
            Ps[r * SROW + tx * 4 + 1] = p1;
            Ps[r * SROW + tx * 4 + 2] = p2;
            Ps[r * SROW + tx * 4 + 3] = p3;
        }
        __syncthreads();

        // O += P @ V   (thread dims = tx*4..tx*4+3)
#pragma unroll
        for (int k4 = 0; k4 < 16; k4++) {
            float4 pv[4], vv[4];
#pragma unroll
            for (int i = 0; i < 4; i++) pv[i] = *(float4*)&Ps[(ty * 4 + i) * SROW + k4 * 4];
#pragma unroll
            for (int j = 0; j < 4; j++) vv[j] = *(float4*)&Vs[(k4 * 4 + j) * SROW + tx * 4];
#pragma unroll
            for (int i = 0; i < 4; i++) {
                o[i].x = fmaf(pv[i].x, vv[0].x, o[i].x);
                o[i].x = fmaf(pv[i].y, vv[1].x, o[i].x);
                o[i].x = fmaf(pv[i].z, vv[2].x, o[i].x);
                o[i].x = fmaf(pv[i].w, vv[3].x, o[i].x);
                o[i].y = fmaf(pv[i].x, vv[0].y, o[i].y);
                o[i].y = fmaf(pv[i].y, vv[1].y, o[i].y);
                o[i].y = fmaf(pv[i].z, vv[2].y, o[i].y);
                o[i].y = fmaf(pv[i].w, vv[3].y, o[i].y);
                o[i].z = fmaf(pv[i].x, vv[0].z, o[i].z);
                o[i].z = fmaf(pv[i].y, vv[1].z, o[i].z);
                o[i].z = fmaf(pv[i].z, vv[2].z, o[i].z);
                o[i].z = fmaf(pv[i].w, vv[3].z, o[i].z);
                o[i].w = fmaf(pv[i].x, vv[0].w, o[i].w);
                o[i].w = fmaf(pv[i].y, vv[1].w, o[i].w);
                o[i].w = fmaf(pv[i].z, vv[2].w, o[i].w);
                o[i].w = fmaf(pv[i].w, vv[3].w, o[i].w);
            }
        }
        __syncthreads();
    }

    // finalize: O /= l ; store to g_o as [B,N,H,D]
#pragma unroll
    for (int i = 0; i < 4; i++) {
        float inv = 1.0f / l[i];
        int qg = qb * 64 + ty * 4 + i;
        float4 ov = make_float4(o[i].x * inv, o[i].y * inv, o[i].z * inv, o[i].w * inv);
        *(float4*)(g_o + ((size_t)(b * Nn + qg) * Hh + h) * Dd + tx * 4) = ov;
    }
}

// ---------------- GEMM3: out = g_o @ Wout + bout ----------------
__global__ __launch_bounds__(256) void out_gemm(
    const float* __restrict__ Bw, const float* __restrict__ bias,
    float* __restrict__ out)
{
    __shared__ float As[8][128];
    __shared__ float Bs[8][128];

    int tid = threadIdx.x;
    int bm = blockIdx.y * 128;
    int bn = blockIdx.x * 128;
    int tx = tid & 15, ty = tid >> 4;

    float acc[8][8];
#pragma unroll
    for (int i = 0; i < 8; i++)
#pragma unroll
        for (int j = 0; j < 8; j++) acc[i][j] = 0.0f;

    int arow = tid >> 1, ac4 = (tid & 1) * 4;
    int brow = tid >> 5, bc4 = (tid & 31) * 4;
    const float* Aptr = g_o + (size_t)(bm + arow) * Cc + ac4;
    const float* Bptr = Bw + (size_t)brow * Cc + bn + bc4;

    for (int kt = 0; kt < Cc / 8; kt++) {
        float4 av = *(const float4*)Aptr;
        As[ac4 + 0][arow] = av.x;
        As[ac4 + 1][arow] = av.y;
        As[ac4 + 2][arow] = av.z;
        As[ac4 + 3][arow] = av.w;
        *(float4*)&Bs[brow][bc4] = *(const float4*)Bptr;
        __syncthreads();

        float a[8], bb[8];
#pragma unroll
        for (int k = 0; k < 8; k++) {
            *(float4*)&a[0]  = *(const float4*)&As[k][ty * 4];
            *(float4*)&a[4]  = *(const float4*)&As[k][ty * 4 + 64];
            *(float4*)&bb[0] = *(const float4*)&Bs[k][tx * 4];
            *(float4*)&bb[4] = *(const float4*)&Bs[k][tx * 4 + 64];
#pragma unroll
            for (int i = 0; i < 8; i++)
#pragma unroll
                for (int j = 0; j < 8; j++) acc[i][j] = fmaf(a[i], bb[j], acc[i][j]);
        }
        __syncthreads();
        Aptr += 8;
        Bptr += 8 * Cc;
    }

#pragma unroll
    for (int s = 0; s < 2; s++) {
#pragma unroll
        for (int i = 0; i < 4; i++) {
            int row = bm + s * 64 + ty * 4 + i;
#pragma unroll
            for (int t = 0; t < 2; t++) {
                int col = bn + t * 64 + tx * 4;
                float4 bi = *(const float4*)&bias[col];
                float4 r4 = make_float4(acc[s * 4 + i][t * 4 + 0] + bi.x,
                                        acc[s * 4 + i][t * 4 + 1] + bi.y,
                                        acc[s * 4 + i][t * 4 + 2] + bi.z,
                                        acc[s * 4 + i][t * 4 + 3] + bi.w);
                *(float4*)(out + (size_t)row * Cc + col) = r4;
            }
        }
    }
}

// ---------------- launch ----------------
extern "C" void kernel_launch(void* const* d_in, const int* in_sizes, int n_in,
                              void* d_out, int out_size)
{
    (void)in_sizes; (void)n_in; (void)out_size;
    const float* x    = (const float*)d_in[0];
    const float* Wqkv = (const float*)d_in[1];
    const float* Wout = (const float*)d_in[2];
    const float* bout = (const float*)d_in[3];
    float* out = (float*)d_out;

    const int smem_attn = 4 * 64 * SROW * (int)sizeof(float); // 69632 B
    cudaFuncSetAttribute(flash_attn_kernel,
                         cudaFuncAttributeMaxDynamicSharedMemorySize, smem_attn);

    rope_init_kernel<<<(Nn * (Dd/2) + 255) / 256, 256>>>();
    qkv_rope_gemm<<<dim3(K3 / 128, Mtot / 128), 256>>>(x, Wqkv);
    flash_attn_kernel<<<dim3(Nn / 64, Bb * Hh), 256, smem_attn>>>();
    out_gemm<<<dim3(Cc / 128, Mtot / 128), 256>>>(Wout, bout, out);
}